// round 6
// baseline (speedup 1.0000x reference)
#include <cuda_runtime.h>
#include <cuda_fp16.h>

#define SB 2
#define SX 160
#define SY 192
#define SZ 160
#define WIN 21
#define HALF 10
#define NF 9830400ull          // SB*SX*SY*SZ
#define YP (SY / 2)            // 96 y-pairs
#define YSEG 2
#define YL (SY / YSEG)         // 96
#define XSEG 4
#define XLEN (SX / XSEG)       // 40
#define NPART (SB * YP * XSEG) // 768
#define LPAD (SZ + 2 * HALF)   // 180
#define S1N (SZ + 18)          // stage1 physical range
#define RDEP 11                // ring depth in y-PAIRS (covers 22 lines)
#define NBLK_AB (SB * SX * YSEG)

// 4 channels packed as half2 (lane = y parity): x=(I), y=(J), z=(I2), w=(J2)
struct __align__(16) HQ { __half2 x, y, z, w; };

__device__ HQ g_q2[NF / 2];            // y-pair-packed output of passAB
__device__ __half2 g_e2[NF / 2];       // IJ channel
__device__ HQ g_rq[NBLK_AB * RDEP * SZ];      // gmem ring (L2-resident)
__device__ __half2 g_re[NBLK_AB * RDEP * SZ];
__device__ double g_part[NPART];
__device__ int g_count;

// ---------------------------------------------------------------------------
// Fused pass A+B, y-pair packed. z-filter = 3-tap then 7-tap-stride-3 packed
// HADD2 stages (both y-lines at once). y-filter = per-thread fp32 running
// sums; the 21-line-ago subtrahend comes from a gmem pair-ring (lane-
// selective reads of slots s and s+1). Thread == z.
// ---------------------------------------------------------------------------
__global__ __launch_bounds__(SZ, 8) void passAB(const float* __restrict__ I,
                                                const float* __restrict__ J) {
    __shared__ HQ      lQ[LPAD];
    __shared__ __half2 lE[LPAD];
    __shared__ HQ      s1Q[S1N];
    __shared__ __half2 s1E[S1N];

    const int z = threadIdx.x;
    int bid = blockIdx.x;
    const int seg = bid % YSEG;
    int t = bid / YSEG;
    const int x = t % SX;
    const int b = t / SX;

    if (z < HALF) {
        HQ z4;
        z4.x = __floats2half2_rn(0.f, 0.f);
        z4.y = z4.x; z4.z = z4.x; z4.w = z4.x;
        lQ[z] = z4; lQ[SZ + HALF + z] = z4;
        lE[z] = z4.x; lE[SZ + HALF + z] = z4.x;
    }

    const int y0 = seg * YL;
    const int y1 = y0 + YL;
    const int ystart = (y0 - HALF > 0) ? (y0 - HALF) : 0;  // even
    const size_t planeBase = ((size_t)(b * SX + x)) * SY * SZ;
    const size_t ringBase = (size_t)bid * RDEP;

    float c0 = 0.f, c1 = 0.f, c2 = 0.f, c3 = 0.f, c4 = 0.f;
    int it = 0;

    __syncthreads();

    for (int y = ystart; y < y1 + HALF; y += 2) {
        // ---- phase 0: stage a packed y-pair + products ----
        float i0 = 0.f, j0 = 0.f, i1 = 0.f, j1 = 0.f;
        if (y < SY) {
            size_t o = planeBase + (size_t)y * SZ + z;
            i0 = I[o]; j0 = J[o];
        }
        if (y + 1 < SY) {
            size_t o = planeBase + (size_t)(y + 1) * SZ + z;
            i1 = I[o]; j1 = J[o];
        }
        {
            HQ h;
            h.x = __floats2half2_rn(i0, i1);
            h.y = __floats2half2_rn(j0, j1);
            h.z = __hmul2(h.x, h.x);
            h.w = __hmul2(h.y, h.y);
            lQ[HALF + z] = h;
            lE[HALF + z] = __hmul2(h.x, h.y);
        }
        __syncthreads();

        // ---- phase 1: 3-tap stage (both lines at once) ----
        {
            const int i = z;
            HQ a0 = lQ[i], a1 = lQ[i + 1], a2 = lQ[i + 2];
            HQ r;
            r.x = __hadd2(__hadd2(a0.x, a1.x), a2.x);
            r.y = __hadd2(__hadd2(a0.y, a1.y), a2.y);
            r.z = __hadd2(__hadd2(a0.z, a1.z), a2.z);
            r.w = __hadd2(__hadd2(a0.w, a1.w), a2.w);
            s1Q[i] = r;
            s1E[i] = __hadd2(__hadd2(lE[i], lE[i + 1]), lE[i + 2]);
        }
        if (z < S1N - SZ) {
            const int i = SZ + z;
            HQ a0 = lQ[i], a1 = lQ[i + 1], a2 = lQ[i + 2];
            HQ r;
            r.x = __hadd2(__hadd2(a0.x, a1.x), a2.x);
            r.y = __hadd2(__hadd2(a0.y, a1.y), a2.y);
            r.z = __hadd2(__hadd2(a0.z, a1.z), a2.z);
            r.w = __hadd2(__hadd2(a0.w, a1.w), a2.w);
            s1Q[i] = r;
            s1E[i] = __hadd2(__hadd2(lE[i], lE[i + 1]), lE[i + 2]);
        }
        __syncthreads();

        // ---- phase 2: 7-tap stride-3 stage ----
        HQ s = s1Q[z];
        __half2 e = s1E[z];
#pragma unroll
        for (int j = 3; j <= 18; j += 3) {
            HQ v = s1Q[z + j];
            s.x = __hadd2(s.x, v.x);
            s.y = __hadd2(s.y, v.y);
            s.z = __hadd2(s.z, v.z);
            s.w = __hadd2(s.w, v.w);
            e = __hadd2(e, s1E[z + j]);
        }

        // ---- ring + y running sums ----
        const int slot = it % RDEP;
        const int slotn = (slot + 1 == RDEP) ? 0 : slot + 1;
        const size_t ro = (ringBase + slot) * SZ + z;
        const size_t rn = (ringBase + slotn) * SZ + z;

        float d0 = 0.f, d1 = 0.f, d2 = 0.f, d3 = 0.f, d4 = 0.f;   // lane1 of slot
        float n0 = 0.f, n1 = 0.f, n2 = 0.f, n3 = 0.f, n4 = 0.f;   // lane0 of slot+1
        const int dy = y - ystart;
        if (dy >= 22) {
            HQ h = g_rq[ro]; __half2 he = g_re[ro];
            d0 = __high2float(h.x); d1 = __high2float(h.y);
            d2 = __high2float(h.z); d3 = __high2float(h.w);
            d4 = __high2float(he);
        }
        if (dy >= 20) {
            HQ h = g_rq[rn]; __half2 he = g_re[rn];
            n0 = __low2float(h.x); n1 = __low2float(h.y);
            n2 = __low2float(h.z); n3 = __low2float(h.w);
            n4 = __low2float(he);
        }
        g_rq[ro] = s;
        g_re[ro] = e;

        // line0 (y): add lane0, sub lane1 of old pair
        c0 += __low2float(s.x) - d0;
        c1 += __low2float(s.y) - d1;
        c2 += __low2float(s.z) - d2;
        c3 += __low2float(s.w) - d3;
        c4 += __low2float(e)   - d4;
        const float a0s = c0, a1s = c1, a2s = c2, a3s = c3, a4s = c4;
        // line1 (y+1): add lane1, sub lane0 of next-old pair
        c0 += __high2float(s.x) - n0;
        c1 += __high2float(s.y) - n1;
        c2 += __high2float(s.z) - n2;
        c3 += __high2float(s.w) - n3;
        c4 += __high2float(e)   - n4;

        const int yo = y - HALF;
        if (yo >= y0) {
            size_t qidx = (((size_t)(b * SX + x)) * YP + (yo >> 1)) * SZ + z;
            HQ w;
            w.x = __floats2half2_rn(a0s, c0);
            w.y = __floats2half2_rn(a1s, c1);
            w.z = __floats2half2_rn(a2s, c2);
            w.w = __floats2half2_rn(a3s, c3);
            g_q2[qidx] = w;
            g_e2[qidx] = __floats2half2_rn(a4s, c4);
        }
        it++;
    }
}

// ---------------------------------------------------------------------------
// Pass C: x box filter over y-pair-packed data (two y-lines per load).
// Running sums per lane in fp32; unroll-4 with batched loads (MLP 8).
// Deterministic partials; last block does a fixed-order final reduction.
// ---------------------------------------------------------------------------
__global__ __launch_bounds__(SZ) void passC(float* __restrict__ out) {
    int bid = blockIdx.x;
    const int seg = bid % XSEG;
    int t = bid / XSEG;
    const int yp = t % YP;
    const int b = t / YP;
    const int z = threadIdx.x;

    const int x0 = seg * XLEN;
    const size_t strideX = (size_t)YP * SZ;
    const size_t base = ((size_t)b * SX) * strideX + (size_t)yp * SZ + z;

    float2 sI = {0.f, 0.f}, sJ = {0.f, 0.f}, sI2 = {0.f, 0.f},
           sJ2 = {0.f, 0.f}, sIJ = {0.f, 0.f};
#pragma unroll
    for (int k = 0; k < WIN; k++) {
        const int xx = x0 - HALF + k;
        if (xx >= 0 && xx < SX) {
            size_t o = base + (size_t)xx * strideX;
            HQ h = g_q2[o];
            __half2 e = g_e2[o];
            float2 f;
            f = __half22float2(h.x); sI.x += f.x; sI.y += f.y;
            f = __half22float2(h.y); sJ.x += f.x; sJ.y += f.y;
            f = __half22float2(h.z); sI2.x += f.x; sI2.y += f.y;
            f = __half22float2(h.w); sJ2.x += f.x; sJ2.y += f.y;
            f = __half22float2(e);   sIJ.x += f.x; sIJ.y += f.y;
        }
    }

    const float inv_n = 1.0f / (float)(WIN * WIN * WIN);
    float acc = 0.f;

    for (int xb = 0; xb < XLEN; xb += 4) {
        HQ ha[4], hr[4];
        __half2 ea[4], er[4];
#pragma unroll
        for (int j = 0; j < 4; j++) {
            const int xa = x0 + xb + j + HALF + 1;
            ha[j].x = __floats2half2_rn(0.f, 0.f);
            ha[j].y = ha[j].x; ha[j].z = ha[j].x; ha[j].w = ha[j].x;
            ea[j] = ha[j].x;
            if (xa < SX) {
                size_t o = base + (size_t)xa * strideX;
                ha[j] = g_q2[o]; ea[j] = g_e2[o];
            }
        }
#pragma unroll
        for (int j = 0; j < 4; j++) {
            const int xr = x0 + xb + j - HALF;
            hr[j].x = __floats2half2_rn(0.f, 0.f);
            hr[j].y = hr[j].x; hr[j].z = hr[j].x; hr[j].w = hr[j].x;
            er[j] = hr[j].x;
            if (xr >= 0) {
                size_t o = base + (size_t)xr * strideX;
                hr[j] = g_q2[o]; er[j] = g_e2[o];
            }
        }
#pragma unroll
        for (int j = 0; j < 4; j++) {
            // cc for both y-lanes
#pragma unroll
            for (int ln = 0; ln < 2; ln++) {
                float t0 = ln ? sI.y : sI.x;
                float t1 = ln ? sJ.y : sJ.x;
                float t2 = ln ? sI2.y : sI2.x;
                float t3 = ln ? sJ2.y : sJ2.x;
                float t4 = ln ? sIJ.y : sIJ.x;
                float cross = t4 - t0 * t1 * inv_n;
                float Ivar  = t2 - t0 * t0 * inv_n;
                float Jvar  = t3 - t1 * t1 * inv_n;
                acc += (cross * cross) / (Ivar * Jvar + 1e-5f);
            }
            float2 fa, fr;
            fa = __half22float2(ha[j].x); fr = __half22float2(hr[j].x);
            sI.x += fa.x - fr.x;  sI.y += fa.y - fr.y;
            fa = __half22float2(ha[j].y); fr = __half22float2(hr[j].y);
            sJ.x += fa.x - fr.x;  sJ.y += fa.y - fr.y;
            fa = __half22float2(ha[j].z); fr = __half22float2(hr[j].z);
            sI2.x += fa.x - fr.x; sI2.y += fa.y - fr.y;
            fa = __half22float2(ha[j].w); fr = __half22float2(hr[j].w);
            sJ2.x += fa.x - fr.x; sJ2.y += fa.y - fr.y;
            fa = __half22float2(ea[j]);   fr = __half22float2(er[j]);
            sIJ.x += fa.x - fr.x; sIJ.y += fa.y - fr.y;
        }
    }

    // deterministic block reduction (160 threads = 5 warps)
    __shared__ float wsum[SZ / 32];
    __shared__ int isLast;
    float v = acc;
#pragma unroll
    for (int off = 16; off; off >>= 1)
        v += __shfl_down_sync(0xffffffffu, v, off);
    if ((threadIdx.x & 31) == 0) wsum[threadIdx.x >> 5] = v;
    __syncthreads();
    if (threadIdx.x == 0) {
        double tot = 0.0;
#pragma unroll
        for (int w = 0; w < SZ / 32; w++) tot += (double)wsum[w];
        g_part[bid] = tot;
        __threadfence();
        int n = atomicAdd(&g_count, 1);
        isLast = (n == NPART - 1);
    }
    __syncthreads();

    if (isLast) {
        __shared__ double sh[256];
        double cv = 0.0;
        const int chunk = 5;                 // 160 * 5 = 800 >= 768
        int lo = threadIdx.x * chunk;
        for (int i = lo; i < lo + chunk && i < NPART; ++i)
            cv += g_part[i];
        sh[threadIdx.x] = cv;
        if (threadIdx.x < 256 - SZ) sh[SZ + threadIdx.x] = 0.0;
        __syncthreads();
        for (int s = 128; s; s >>= 1) {
            if (threadIdx.x < s) sh[threadIdx.x] += sh[threadIdx.x + s];
            __syncthreads();
        }
        if (threadIdx.x == 0) {
            out[0] = (float)(1.0 - sh[0] / (double)NF);
            g_count = 0;                      // reset for next graph replay
        }
    }
}

extern "C" void kernel_launch(void* const* d_in, const int* in_sizes, int n_in,
                              void* d_out, int out_size) {
    const float* I = (const float*)d_in[0];
    const float* J = (const float*)d_in[1];
    float* out = (float*)d_out;

    passAB<<<NBLK_AB, SZ>>>(I, J);
    passC<<<NPART, SZ>>>(out);
}

// round 7
// speedup vs baseline: 1.1304x; 1.1304x over previous
#include <cuda_runtime.h>
#include <cuda_fp16.h>

#define SB 2
#define SX 160
#define SY 192
#define SZ 160
#define WIN 21
#define HALF 10
#define NF 9830400ull          // SB*SX*SY*SZ
#define YP (SY / 2)            // 96 y-pairs
#define YSEG 2
#define YL (SY / YSEG)         // 96
#define XSEG 4
#define XLEN (SX / XSEG)       // 40
#define NPART (SB * YP * XSEG) // 768
#define LPAD (SZ + 2 * HALF)   // 180
#define S1N (SZ + 18)          // stage1 physical range
#define RDEP 11                // ring depth in y-PAIRS (covers 22 lines)
#define NBLK_AB (SB * SX * YSEG)

// 4 channels packed as half2 (lane = y parity): x=(I), y=(J), z=(I2), w=(J2)
struct __align__(16) HQ { __half2 x, y, z, w; };

__device__ HQ g_q2[NF / 2];            // y-pair-packed output of passAB
__device__ __half2 g_e2[NF / 2];       // IJ channel
__device__ double g_part[NPART];
__device__ int g_count;

// ---------------------------------------------------------------------------
// Fused pass A+B, y-pair packed, smem ring. z-filter = 3-tap stage then
// 7-tap-stride-3 stage, packed HADD2 (both y-lines at once). y-filter =
// per-thread fp32 running sums; subtrahends come from a 11-pair smem ring
// with lane-selective reads of slots s and s+1 (odd window 21 straddles two
// pairs). Ring stores exactly what was added -> exact cancellation.
// Thread == z; one y-pair per 2 barriers.
// ---------------------------------------------------------------------------
__global__ __launch_bounds__(SZ) void passAB(const float* __restrict__ I,
                                             const float* __restrict__ J) {
    __shared__ HQ      lQ[LPAD];
    __shared__ __half2 lE[LPAD];
    __shared__ HQ      s1Q[S1N];
    __shared__ __half2 s1E[S1N];
    __shared__ HQ      ringQ[RDEP][SZ];
    __shared__ __half2 ringE[RDEP][SZ];

    const int z = threadIdx.x;
    int bid = blockIdx.x;
    const int seg = bid % YSEG;
    int t = bid / YSEG;
    const int x = t % SX;
    const int b = t / SX;

    if (z < HALF) {
        HQ z4;
        z4.x = __floats2half2_rn(0.f, 0.f);
        z4.y = z4.x; z4.z = z4.x; z4.w = z4.x;
        lQ[z] = z4; lQ[SZ + HALF + z] = z4;
        lE[z] = z4.x; lE[SZ + HALF + z] = z4.x;
    }

    const int y0 = seg * YL;
    const int y1 = y0 + YL;
    const int ystart = (y0 - HALF > 0) ? (y0 - HALF) : 0;  // even
    const size_t planeBase = ((size_t)(b * SX + x)) * SY * SZ;

    float c0 = 0.f, c1 = 0.f, c2 = 0.f, c3 = 0.f, c4 = 0.f;
    int it = 0;

    __syncthreads();

    for (int y = ystart; y < y1 + HALF; y += 2) {
        // ---- phase 0: stage a packed y-pair + products ----
        float i0 = 0.f, j0 = 0.f, i1 = 0.f, j1 = 0.f;
        if (y < SY) {
            size_t o = planeBase + (size_t)y * SZ + z;
            i0 = I[o]; j0 = J[o];
        }
        if (y + 1 < SY) {
            size_t o = planeBase + (size_t)(y + 1) * SZ + z;
            i1 = I[o]; j1 = J[o];
        }
        {
            HQ h;
            h.x = __floats2half2_rn(i0, i1);
            h.y = __floats2half2_rn(j0, j1);
            h.z = __hmul2(h.x, h.x);
            h.w = __hmul2(h.y, h.y);
            lQ[HALF + z] = h;
            lE[HALF + z] = __hmul2(h.x, h.y);
        }
        __syncthreads();

        // ---- phase 1: 3-tap stage (both lines at once) ----
        {
            const int i = z;
            HQ a0 = lQ[i], a1 = lQ[i + 1], a2 = lQ[i + 2];
            HQ r;
            r.x = __hadd2(__hadd2(a0.x, a1.x), a2.x);
            r.y = __hadd2(__hadd2(a0.y, a1.y), a2.y);
            r.z = __hadd2(__hadd2(a0.z, a1.z), a2.z);
            r.w = __hadd2(__hadd2(a0.w, a1.w), a2.w);
            s1Q[i] = r;
            s1E[i] = __hadd2(__hadd2(lE[i], lE[i + 1]), lE[i + 2]);
        }
        if (z < S1N - SZ) {
            const int i = SZ + z;
            HQ a0 = lQ[i], a1 = lQ[i + 1], a2 = lQ[i + 2];
            HQ r;
            r.x = __hadd2(__hadd2(a0.x, a1.x), a2.x);
            r.y = __hadd2(__hadd2(a0.y, a1.y), a2.y);
            r.z = __hadd2(__hadd2(a0.z, a1.z), a2.z);
            r.w = __hadd2(__hadd2(a0.w, a1.w), a2.w);
            s1Q[i] = r;
            s1E[i] = __hadd2(__hadd2(lE[i], lE[i + 1]), lE[i + 2]);
        }
        __syncthreads();

        // ---- phase 2: 7-tap stride-3 stage ----
        HQ s = s1Q[z];
        __half2 e = s1E[z];
#pragma unroll
        for (int j = 3; j <= 18; j += 3) {
            HQ v = s1Q[z + j];
            s.x = __hadd2(s.x, v.x);
            s.y = __hadd2(s.y, v.y);
            s.z = __hadd2(s.z, v.z);
            s.w = __hadd2(s.w, v.w);
            e = __hadd2(e, s1E[z + j]);
        }

        // ---- smem ring + y running sums (per-thread column, no sync) ----
        const int slot = it % RDEP;
        const int slotn = (slot + 1 == RDEP) ? 0 : slot + 1;

        float d0 = 0.f, d1 = 0.f, d2 = 0.f, d3 = 0.f, d4 = 0.f;  // lane1, pair it-11
        float n0 = 0.f, n1 = 0.f, n2 = 0.f, n3 = 0.f, n4 = 0.f;  // lane0, pair it-10
        const int dy = y - ystart;
        if (dy >= 22) {
            HQ h = ringQ[slot][z]; __half2 he = ringE[slot][z];
            d0 = __high2float(h.x); d1 = __high2float(h.y);
            d2 = __high2float(h.z); d3 = __high2float(h.w);
            d4 = __high2float(he);
        }
        if (dy >= 20) {
            HQ h = ringQ[slotn][z]; __half2 he = ringE[slotn][z];
            n0 = __low2float(h.x); n1 = __low2float(h.y);
            n2 = __low2float(h.z); n3 = __low2float(h.w);
            n4 = __low2float(he);
        }
        ringQ[slot][z] = s;
        ringE[slot][z] = e;

        // line0 (y): add lane0 of new pair, sub lane1 of pair it-11
        c0 += __low2float(s.x) - d0;
        c1 += __low2float(s.y) - d1;
        c2 += __low2float(s.z) - d2;
        c3 += __low2float(s.w) - d3;
        c4 += __low2float(e)   - d4;
        const float a0s = c0, a1s = c1, a2s = c2, a3s = c3, a4s = c4;
        // line1 (y+1): add lane1 of new pair, sub lane0 of pair it-10
        c0 += __high2float(s.x) - n0;
        c1 += __high2float(s.y) - n1;
        c2 += __high2float(s.z) - n2;
        c3 += __high2float(s.w) - n3;
        c4 += __high2float(e)   - n4;

        const int yo = y - HALF;
        if (yo >= y0) {
            size_t qidx = (((size_t)(b * SX + x)) * YP + (yo >> 1)) * SZ + z;
            HQ w;
            w.x = __floats2half2_rn(a0s, c0);
            w.y = __floats2half2_rn(a1s, c1);
            w.z = __floats2half2_rn(a2s, c2);
            w.w = __floats2half2_rn(a3s, c3);
            g_q2[qidx] = w;
            g_e2[qidx] = __floats2half2_rn(a4s, c4);
        }
        it++;
    }
}

// ---------------------------------------------------------------------------
// Pass C: x box filter over y-pair-packed data (two y-lines per load).
// Running sums per lane in fp32; unroll-4 with batched loads (MLP 8).
// Deterministic partials; last block does a fixed-order final reduction.
// ---------------------------------------------------------------------------
__global__ __launch_bounds__(SZ) void passC(float* __restrict__ out) {
    int bid = blockIdx.x;
    const int seg = bid % XSEG;
    int t = bid / XSEG;
    const int yp = t % YP;
    const int b = t / YP;
    const int z = threadIdx.x;

    const int x0 = seg * XLEN;
    const size_t strideX = (size_t)YP * SZ;
    const size_t base = ((size_t)b * SX) * strideX + (size_t)yp * SZ + z;

    float2 sI = {0.f, 0.f}, sJ = {0.f, 0.f}, sI2 = {0.f, 0.f},
           sJ2 = {0.f, 0.f}, sIJ = {0.f, 0.f};
#pragma unroll
    for (int k = 0; k < WIN; k++) {
        const int xx = x0 - HALF + k;
        if (xx >= 0 && xx < SX) {
            size_t o = base + (size_t)xx * strideX;
            HQ h = g_q2[o];
            __half2 e = g_e2[o];
            float2 f;
            f = __half22float2(h.x); sI.x += f.x; sI.y += f.y;
            f = __half22float2(h.y); sJ.x += f.x; sJ.y += f.y;
            f = __half22float2(h.z); sI2.x += f.x; sI2.y += f.y;
            f = __half22float2(h.w); sJ2.x += f.x; sJ2.y += f.y;
            f = __half22float2(e);   sIJ.x += f.x; sIJ.y += f.y;
        }
    }

    const float inv_n = 1.0f / (float)(WIN * WIN * WIN);
    float acc = 0.f;

    for (int xb = 0; xb < XLEN; xb += 4) {
        HQ ha[4], hr[4];
        __half2 ea[4], er[4];
#pragma unroll
        for (int j = 0; j < 4; j++) {
            const int xa = x0 + xb + j + HALF + 1;
            ha[j].x = __floats2half2_rn(0.f, 0.f);
            ha[j].y = ha[j].x; ha[j].z = ha[j].x; ha[j].w = ha[j].x;
            ea[j] = ha[j].x;
            if (xa < SX) {
                size_t o = base + (size_t)xa * strideX;
                ha[j] = g_q2[o]; ea[j] = g_e2[o];
            }
        }
#pragma unroll
        for (int j = 0; j < 4; j++) {
            const int xr = x0 + xb + j - HALF;
            hr[j].x = __floats2half2_rn(0.f, 0.f);
            hr[j].y = hr[j].x; hr[j].z = hr[j].x; hr[j].w = hr[j].x;
            er[j] = hr[j].x;
            if (xr >= 0) {
                size_t o = base + (size_t)xr * strideX;
                hr[j] = g_q2[o]; er[j] = g_e2[o];
            }
        }
#pragma unroll
        for (int j = 0; j < 4; j++) {
#pragma unroll
            for (int ln = 0; ln < 2; ln++) {
                float t0 = ln ? sI.y : sI.x;
                float t1 = ln ? sJ.y : sJ.x;
                float t2 = ln ? sI2.y : sI2.x;
                float t3 = ln ? sJ2.y : sJ2.x;
                float t4 = ln ? sIJ.y : sIJ.x;
                float cross = t4 - t0 * t1 * inv_n;
                float Ivar  = t2 - t0 * t0 * inv_n;
                float Jvar  = t3 - t1 * t1 * inv_n;
                acc += (cross * cross) / (Ivar * Jvar + 1e-5f);
            }
            float2 fa, fr;
            fa = __half22float2(ha[j].x); fr = __half22float2(hr[j].x);
            sI.x += fa.x - fr.x;  sI.y += fa.y - fr.y;
            fa = __half22float2(ha[j].y); fr = __half22float2(hr[j].y);
            sJ.x += fa.x - fr.x;  sJ.y += fa.y - fr.y;
            fa = __half22float2(ha[j].z); fr = __half22float2(hr[j].z);
            sI2.x += fa.x - fr.x; sI2.y += fa.y - fr.y;
            fa = __half22float2(ha[j].w); fr = __half22float2(hr[j].w);
            sJ2.x += fa.x - fr.x; sJ2.y += fa.y - fr.y;
            fa = __half22float2(ea[j]);   fr = __half22float2(er[j]);
            sIJ.x += fa.x - fr.x; sIJ.y += fa.y - fr.y;
        }
    }

    // deterministic block reduction (160 threads = 5 warps)
    __shared__ float wsum[SZ / 32];
    __shared__ int isLast;
    float v = acc;
#pragma unroll
    for (int off = 16; off; off >>= 1)
        v += __shfl_down_sync(0xffffffffu, v, off);
    if ((threadIdx.x & 31) == 0) wsum[threadIdx.x >> 5] = v;
    __syncthreads();
    if (threadIdx.x == 0) {
        double tot = 0.0;
#pragma unroll
        for (int w = 0; w < SZ / 32; w++) tot += (double)wsum[w];
        g_part[bid] = tot;
        __threadfence();
        int n = atomicAdd(&g_count, 1);
        isLast = (n == NPART - 1);
    }
    __syncthreads();

    if (isLast) {
        __shared__ double sh[256];
        double cv = 0.0;
        const int chunk = 5;                 // 160 * 5 = 800 >= 768
        int lo = threadIdx.x * chunk;
        for (int i = lo; i < lo + chunk && i < NPART; ++i)
            cv += g_part[i];
        sh[threadIdx.x] = cv;
        if (threadIdx.x < 256 - SZ) sh[SZ + threadIdx.x] = 0.0;
        __syncthreads();
        for (int s = 128; s; s >>= 1) {
            if (threadIdx.x < s) sh[threadIdx.x] += sh[threadIdx.x + s];
            __syncthreads();
        }
        if (threadIdx.x == 0) {
            out[0] = (float)(1.0 - sh[0] / (double)NF);
            g_count = 0;                      // reset for next graph replay
        }
    }
}

extern "C" void kernel_launch(void* const* d_in, const int* in_sizes, int n_in,
                              void* d_out, int out_size) {
    const float* I = (const float*)d_in[0];
    const float* J = (const float*)d_in[1];
    float* out = (float*)d_out;

    passAB<<<NBLK_AB, SZ>>>(I, J);
    passC<<<NPART, SZ>>>(out);
}

// round 8
// speedup vs baseline: 1.1816x; 1.0453x over previous
#include <cuda_runtime.h>
#include <cuda_fp16.h>

#define SB 2
#define SX 160
#define SY 192
#define SZ 160
#define WIN 21
#define HALF 10
#define NF 9830400ull          // SB*SX*SY*SZ
#define YP (SY / 2)            // 96 y-pairs
#define YSEG 2
#define YL (SY / YSEG)         // 96
#define XSEG 4
#define XLEN (SX / XSEG)       // 40
#define NPART (SB * YP * XSEG) // 768
#define LPAD (SZ + 2 * HALF)   // 180
#define S1N (SZ + 18)          // stage1 physical range
#define RDEP 11                // ring depth in y-PAIRS (covers 22 lines)
#define NBLK_AB (SB * SX * YSEG)

// 4 channels packed as half2 (lane = y parity): x=(I), y=(J), z=(I2), w=(J2)
struct __align__(16) HQ { __half2 x, y, z, w; };

__device__ HQ g_q2[NF / 2];            // y-pair-packed output of passAB
__device__ __half2 g_e2[NF / 2];       // IJ channel
__device__ HQ g_rq[(size_t)NBLK_AB * RDEP * SZ];      // gmem ring (L2-resident)
__device__ __half2 g_re[(size_t)NBLK_AB * RDEP * SZ];
__device__ double g_part[NPART];
__device__ int g_count;

// ---------------------------------------------------------------------------
// Fused pass A+B, y-pair packed. z-filter = 3-tap stage then 7-tap-stride-3
// stage, packed HADD2 (both y-lines at once). y-filter = per-thread fp32
// running sums; subtrahends come from a GMEM pair-ring whose loads are
// PREFETCHED at iteration start and consumed after phase 2 (two barriers +
// all tap work later), hiding L2 latency. Next pair's input lines are also
// prefetched one iteration ahead. smem = 7.2 KB -> high occupancy.
// Ring stores exactly what was added -> exact cancellation.
// ---------------------------------------------------------------------------
__global__ __launch_bounds__(SZ) void passAB(const float* __restrict__ I,
                                             const float* __restrict__ J) {
    __shared__ HQ      lQ[LPAD];
    __shared__ __half2 lE[LPAD];
    __shared__ HQ      s1Q[S1N];
    __shared__ __half2 s1E[S1N];

    const int z = threadIdx.x;
    int bid = blockIdx.x;
    const int seg = bid % YSEG;
    int t = bid / YSEG;
    const int x = t % SX;
    const int b = t / SX;

    if (z < HALF) {
        HQ z4;
        z4.x = __floats2half2_rn(0.f, 0.f);
        z4.y = z4.x; z4.z = z4.x; z4.w = z4.x;
        lQ[z] = z4; lQ[SZ + HALF + z] = z4;
        lE[z] = z4.x; lE[SZ + HALF + z] = z4.x;
    }

    const int y0 = seg * YL;
    const int y1 = y0 + YL;
    const int ystart = (y0 - HALF > 0) ? (y0 - HALF) : 0;  // even
    const size_t planeBase = ((size_t)(b * SX + x)) * SY * SZ;
    const size_t ringBase = (size_t)bid * RDEP;

    float c0 = 0.f, c1 = 0.f, c2 = 0.f, c3 = 0.f, c4 = 0.f;

    // preload the first pair's input lines
    float pi0 = 0.f, pj0 = 0.f, pi1 = 0.f, pj1 = 0.f;
    {
        size_t o = planeBase + (size_t)ystart * SZ + z;
        pi0 = I[o]; pj0 = J[o];
        if (ystart + 1 < SY) {
            size_t o1 = o + SZ;
            pi1 = I[o1]; pj1 = J[o1];
        }
    }

    __syncthreads();

    int it = 0;
    for (int y = ystart; y < y1 + HALF; y += 2, ++it) {
        // ---- ring prefetch (consumed after phase 2) ----
        const int slot = it % RDEP;
        const int slotn = (slot + 1 == RDEP) ? 0 : slot + 1;
        const size_t ro = (ringBase + slot) * SZ + z;
        const size_t rn = (ringBase + slotn) * SZ + z;
        const bool haveD = (it >= 11);   // lane1 of pair it-11
        const bool haveN = (it >= 10);   // lane0 of pair it-10
        HQ hd, hn; __half2 hed, hen;
        if (haveD) { hd = g_rq[ro]; hed = g_re[ro]; }
        if (haveN) { hn = g_rq[rn]; hen = g_re[rn]; }

        // ---- phase 0: products of the preloaded pair, stage to smem ----
        {
            HQ h;
            h.x = __floats2half2_rn(pi0, pi1);
            h.y = __floats2half2_rn(pj0, pj1);
            h.z = __hmul2(h.x, h.x);
            h.w = __hmul2(h.y, h.y);
            lQ[HALF + z] = h;
            lE[HALF + z] = __hmul2(h.x, h.y);
        }

        // ---- prefetch next pair's input lines ----
        pi0 = 0.f; pj0 = 0.f; pi1 = 0.f; pj1 = 0.f;
        {
            const int yn = y + 2;
            if (yn < y1 + HALF) {
                if (yn < SY) {
                    size_t o = planeBase + (size_t)yn * SZ + z;
                    pi0 = I[o]; pj0 = J[o];
                }
                if (yn + 1 < SY) {
                    size_t o = planeBase + (size_t)(yn + 1) * SZ + z;
                    pi1 = I[o]; pj1 = J[o];
                }
            }
        }
        __syncthreads();

        // ---- phase 1: 3-tap stage (both lines at once) ----
        {
            const int i = z;
            HQ a0 = lQ[i], a1 = lQ[i + 1], a2 = lQ[i + 2];
            HQ r;
            r.x = __hadd2(__hadd2(a0.x, a1.x), a2.x);
            r.y = __hadd2(__hadd2(a0.y, a1.y), a2.y);
            r.z = __hadd2(__hadd2(a0.z, a1.z), a2.z);
            r.w = __hadd2(__hadd2(a0.w, a1.w), a2.w);
            s1Q[i] = r;
            s1E[i] = __hadd2(__hadd2(lE[i], lE[i + 1]), lE[i + 2]);
        }
        if (z < S1N - SZ) {
            const int i = SZ + z;
            HQ a0 = lQ[i], a1 = lQ[i + 1], a2 = lQ[i + 2];
            HQ r;
            r.x = __hadd2(__hadd2(a0.x, a1.x), a2.x);
            r.y = __hadd2(__hadd2(a0.y, a1.y), a2.y);
            r.z = __hadd2(__hadd2(a0.z, a1.z), a2.z);
            r.w = __hadd2(__hadd2(a0.w, a1.w), a2.w);
            s1Q[i] = r;
            s1E[i] = __hadd2(__hadd2(lE[i], lE[i + 1]), lE[i + 2]);
        }
        __syncthreads();

        // ---- phase 2: 7-tap stride-3 stage ----
        HQ s = s1Q[z];
        __half2 e = s1E[z];
#pragma unroll
        for (int j = 3; j <= 18; j += 3) {
            HQ v = s1Q[z + j];
            s.x = __hadd2(s.x, v.x);
            s.y = __hadd2(s.y, v.y);
            s.z = __hadd2(s.z, v.z);
            s.w = __hadd2(s.w, v.w);
            e = __hadd2(e, s1E[z + j]);
        }

        // ---- ring write (slot read was prefetched above) ----
        g_rq[ro] = s;
        g_re[ro] = e;

        // ---- consume prefetched subtrahends + y running sums ----
        float d0 = 0.f, d1 = 0.f, d2 = 0.f, d3 = 0.f, d4 = 0.f;
        float n0 = 0.f, n1 = 0.f, n2 = 0.f, n3 = 0.f, n4 = 0.f;
        if (haveD) {
            d0 = __high2float(hd.x); d1 = __high2float(hd.y);
            d2 = __high2float(hd.z); d3 = __high2float(hd.w);
            d4 = __high2float(hed);
        }
        if (haveN) {
            n0 = __low2float(hn.x); n1 = __low2float(hn.y);
            n2 = __low2float(hn.z); n3 = __low2float(hn.w);
            n4 = __low2float(hen);
        }

        // line0 (y): add lane0 of new pair, sub lane1 of pair it-11
        c0 += __low2float(s.x) - d0;
        c1 += __low2float(s.y) - d1;
        c2 += __low2float(s.z) - d2;
        c3 += __low2float(s.w) - d3;
        c4 += __low2float(e)   - d4;
        const float a0s = c0, a1s = c1, a2s = c2, a3s = c3, a4s = c4;
        // line1 (y+1): add lane1 of new pair, sub lane0 of pair it-10
        c0 += __high2float(s.x) - n0;
        c1 += __high2float(s.y) - n1;
        c2 += __high2float(s.z) - n2;
        c3 += __high2float(s.w) - n3;
        c4 += __high2float(e)   - n4;

        const int yo = y - HALF;
        if (yo >= y0) {
            size_t qidx = (((size_t)(b * SX + x)) * YP + (yo >> 1)) * SZ + z;
            HQ w;
            w.x = __floats2half2_rn(a0s, c0);
            w.y = __floats2half2_rn(a1s, c1);
            w.z = __floats2half2_rn(a2s, c2);
            w.w = __floats2half2_rn(a3s, c3);
            g_q2[qidx] = w;
            g_e2[qidx] = __floats2half2_rn(a4s, c4);
        }
    }
}

// ---------------------------------------------------------------------------
// Pass C: x box filter over y-pair-packed data (two y-lines per load).
// Running sums per lane in fp32; unroll-4 with batched loads (MLP 8).
// Deterministic partials; last block does a fixed-order final reduction.
// ---------------------------------------------------------------------------
__global__ __launch_bounds__(SZ, 6) void passC(float* __restrict__ out) {
    int bid = blockIdx.x;
    const int seg = bid % XSEG;
    int t = bid / XSEG;
    const int yp = t % YP;
    const int b = t / YP;
    const int z = threadIdx.x;

    const int x0 = seg * XLEN;
    const size_t strideX = (size_t)YP * SZ;
    const size_t base = ((size_t)b * SX) * strideX + (size_t)yp * SZ + z;

    float2 sI = {0.f, 0.f}, sJ = {0.f, 0.f}, sI2 = {0.f, 0.f},
           sJ2 = {0.f, 0.f}, sIJ = {0.f, 0.f};
#pragma unroll
    for (int k = 0; k < WIN; k++) {
        const int xx = x0 - HALF + k;
        if (xx >= 0 && xx < SX) {
            size_t o = base + (size_t)xx * strideX;
            HQ h = g_q2[o];
            __half2 e = g_e2[o];
            float2 f;
            f = __half22float2(h.x); sI.x += f.x; sI.y += f.y;
            f = __half22float2(h.y); sJ.x += f.x; sJ.y += f.y;
            f = __half22float2(h.z); sI2.x += f.x; sI2.y += f.y;
            f = __half22float2(h.w); sJ2.x += f.x; sJ2.y += f.y;
            f = __half22float2(e);   sIJ.x += f.x; sIJ.y += f.y;
        }
    }

    const float inv_n = 1.0f / (float)(WIN * WIN * WIN);
    float acc = 0.f;

    for (int xb = 0; xb < XLEN; xb += 4) {
        HQ ha[4], hr[4];
        __half2 ea[4], er[4];
#pragma unroll
        for (int j = 0; j < 4; j++) {
            const int xa = x0 + xb + j + HALF + 1;
            ha[j].x = __floats2half2_rn(0.f, 0.f);
            ha[j].y = ha[j].x; ha[j].z = ha[j].x; ha[j].w = ha[j].x;
            ea[j] = ha[j].x;
            if (xa < SX) {
                size_t o = base + (size_t)xa * strideX;
                ha[j] = g_q2[o]; ea[j] = g_e2[o];
            }
        }
#pragma unroll
        for (int j = 0; j < 4; j++) {
            const int xr = x0 + xb + j - HALF;
            hr[j].x = __floats2half2_rn(0.f, 0.f);
            hr[j].y = hr[j].x; hr[j].z = hr[j].x; hr[j].w = hr[j].x;
            er[j] = hr[j].x;
            if (xr >= 0) {
                size_t o = base + (size_t)xr * strideX;
                hr[j] = g_q2[o]; er[j] = g_e2[o];
            }
        }
#pragma unroll
        for (int j = 0; j < 4; j++) {
#pragma unroll
            for (int ln = 0; ln < 2; ln++) {
                float t0 = ln ? sI.y : sI.x;
                float t1 = ln ? sJ.y : sJ.x;
                float t2 = ln ? sI2.y : sI2.x;
                float t3 = ln ? sJ2.y : sJ2.x;
                float t4 = ln ? sIJ.y : sIJ.x;
                float cross = t4 - t0 * t1 * inv_n;
                float Ivar  = t2 - t0 * t0 * inv_n;
                float Jvar  = t3 - t1 * t1 * inv_n;
                acc += (cross * cross) / (Ivar * Jvar + 1e-5f);
            }
            float2 fa, fr;
            fa = __half22float2(ha[j].x); fr = __half22float2(hr[j].x);
            sI.x += fa.x - fr.x;  sI.y += fa.y - fr.y;
            fa = __half22float2(ha[j].y); fr = __half22float2(hr[j].y);
            sJ.x += fa.x - fr.x;  sJ.y += fa.y - fr.y;
            fa = __half22float2(ha[j].z); fr = __half22float2(hr[j].z);
            sI2.x += fa.x - fr.x; sI2.y += fa.y - fr.y;
            fa = __half22float2(ha[j].w); fr = __half22float2(hr[j].w);
            sJ2.x += fa.x - fr.x; sJ2.y += fa.y - fr.y;
            fa = __half22float2(ea[j]);   fr = __half22float2(er[j]);
            sIJ.x += fa.x - fr.x; sIJ.y += fa.y - fr.y;
        }
    }

    // deterministic block reduction (160 threads = 5 warps)
    __shared__ float wsum[SZ / 32];
    __shared__ int isLast;
    float v = acc;
#pragma unroll
    for (int off = 16; off; off >>= 1)
        v += __shfl_down_sync(0xffffffffu, v, off);
    if ((threadIdx.x & 31) == 0) wsum[threadIdx.x >> 5] = v;
    __syncthreads();
    if (threadIdx.x == 0) {
        double tot = 0.0;
#pragma unroll
        for (int w = 0; w < SZ / 32; w++) tot += (double)wsum[w];
        g_part[bid] = tot;
        __threadfence();
        int n = atomicAdd(&g_count, 1);
        isLast = (n == NPART - 1);
    }
    __syncthreads();

    if (isLast) {
        __shared__ double sh[256];
        double cv = 0.0;
        const int chunk = 5;                 // 160 * 5 = 800 >= 768
        int lo = threadIdx.x * chunk;
        for (int i = lo; i < lo + chunk && i < NPART; ++i)
            cv += g_part[i];
        sh[threadIdx.x] = cv;
        if (threadIdx.x < 256 - SZ) sh[SZ + threadIdx.x] = 0.0;
        __syncthreads();
        for (int s = 128; s; s >>= 1) {
            if (threadIdx.x < s) sh[threadIdx.x] += sh[threadIdx.x + s];
            __syncthreads();
        }
        if (threadIdx.x == 0) {
            out[0] = (float)(1.0 - sh[0] / (double)NF);
            g_count = 0;                      // reset for next graph replay
        }
    }
}

extern "C" void kernel_launch(void* const* d_in, const int* in_sizes, int n_in,
                              void* d_out, int out_size) {
    const float* I = (const float*)d_in[0];
    const float* J = (const float*)d_in[1];
    float* out = (float*)d_out;

    passAB<<<NBLK_AB, SZ>>>(I, J);
    passC<<<NPART, SZ>>>(out);
}

// round 9
// speedup vs baseline: 1.2353x; 1.0454x over previous
#include <cuda_runtime.h>
#include <cuda_fp16.h>

#define SB 2
#define SX 160
#define SY 192
#define SZ 160
#define WIN 21
#define HALF 10
#define NF 9830400ull          // SB*SX*SY*SZ
#define YP (SY / 2)            // 96 y-pairs
#define YSEG 2
#define YL (SY / YSEG)         // 96
#define XSEG 4
#define XLEN (SX / XSEG)       // 40
#define NPART (SB * YP * XSEG) // 768
#define LPAD (SZ + 2 * HALF)   // 180
#define S1N (SZ + 18)          // stage1 physical range
#define RDEP 11                // ring depth in y-PAIRS (covers 22 lines)
#define NBLK_AB (SB * SX * YSEG)

// 4 channels packed as half2 (lane = y parity): x=(I), y=(J), z=(I2), w=(J2)
struct __align__(16) HQ { __half2 x, y, z, w; };

__device__ HQ g_q2[NF / 2];            // y-pair-packed output of passAB
__device__ __half2 g_e2[NF / 2];       // IJ channel
__device__ HQ g_rq[(size_t)NBLK_AB * RDEP * SZ];      // gmem ring (L2-resident)
__device__ __half2 g_re[(size_t)NBLK_AB * RDEP * SZ];
__device__ double g_part[NPART];
__device__ int g_count;

// ---------------------------------------------------------------------------
// Fused pass A+B, y-pair packed. z-filter = 3-tap then 7-tap-stride-3 packed
// HADD2 stages (both y-lines at once). y-filter = per-thread running sums in
// NATIVE half (no converts on the chain); subtrahends come from a GMEM
// pair-ring prefetched at iteration start (L2 latency hidden behind two
// barriers + all tap work). Next pair's input lines prefetched one iter ahead.
// ---------------------------------------------------------------------------
__global__ __launch_bounds__(SZ) void passAB(const float* __restrict__ I,
                                             const float* __restrict__ J) {
    __shared__ HQ      lQ[LPAD];
    __shared__ __half2 lE[LPAD];
    __shared__ HQ      s1Q[S1N];
    __shared__ __half2 s1E[S1N];

    const int z = threadIdx.x;
    int bid = blockIdx.x;
    const int seg = bid % YSEG;
    int t = bid / YSEG;
    const int x = t % SX;
    const int b = t / SX;

    const __half2 zero2 = __floats2half2_rn(0.f, 0.f);
    const __half zeroh = __float2half(0.f);

    if (z < HALF) {
        HQ z4; z4.x = zero2; z4.y = zero2; z4.z = zero2; z4.w = zero2;
        lQ[z] = z4; lQ[SZ + HALF + z] = z4;
        lE[z] = zero2; lE[SZ + HALF + z] = zero2;
    }

    const int y0 = seg * YL;
    const int y1 = y0 + YL;
    const int ystart = (y0 - HALF > 0) ? (y0 - HALF) : 0;  // even
    const size_t planeBase = ((size_t)(b * SX + x)) * SY * SZ;
    const size_t ringBase = (size_t)bid * RDEP;

    __half c0 = zeroh, c1 = zeroh, c2 = zeroh, c3 = zeroh, c4 = zeroh;

    // preload the first pair's input lines
    float pi0 = 0.f, pj0 = 0.f, pi1 = 0.f, pj1 = 0.f;
    {
        size_t o = planeBase + (size_t)ystart * SZ + z;
        pi0 = I[o]; pj0 = J[o];
        if (ystart + 1 < SY) {
            size_t o1 = o + SZ;
            pi1 = I[o1]; pj1 = J[o1];
        }
    }

    __syncthreads();

    int it = 0;
    for (int y = ystart; y < y1 + HALF; y += 2, ++it) {
        // ---- ring prefetch (consumed after phase 2) ----
        const int slot = it % RDEP;
        const int slotn = (slot + 1 == RDEP) ? 0 : slot + 1;
        const size_t ro = (ringBase + slot) * SZ + z;
        const size_t rn = (ringBase + slotn) * SZ + z;
        HQ hd, hn; __half2 hed, hen;
        hd.x = zero2; hd.y = zero2; hd.z = zero2; hd.w = zero2; hed = zero2;
        hn = hd; hen = zero2;
        if (it >= 11) { hd = g_rq[ro]; hed = g_re[ro]; }   // lane1 of pair it-11
        if (it >= 10) { hn = g_rq[rn]; hen = g_re[rn]; }   // lane0 of pair it-10

        // ---- phase 0: products of the preloaded pair, stage to smem ----
        {
            HQ h;
            h.x = __floats2half2_rn(pi0, pi1);
            h.y = __floats2half2_rn(pj0, pj1);
            h.z = __hmul2(h.x, h.x);
            h.w = __hmul2(h.y, h.y);
            lQ[HALF + z] = h;
            lE[HALF + z] = __hmul2(h.x, h.y);
        }

        // ---- prefetch next pair's input lines ----
        pi0 = 0.f; pj0 = 0.f; pi1 = 0.f; pj1 = 0.f;
        {
            const int yn = y + 2;
            if (yn < y1 + HALF) {
                if (yn < SY) {
                    size_t o = planeBase + (size_t)yn * SZ + z;
                    pi0 = I[o]; pj0 = J[o];
                }
                if (yn + 1 < SY) {
                    size_t o = planeBase + (size_t)(yn + 1) * SZ + z;
                    pi1 = I[o]; pj1 = J[o];
                }
            }
        }
        __syncthreads();

        // ---- phase 1: 3-tap stage (both lines at once) ----
        {
            const int i = z;
            HQ a0 = lQ[i], a1 = lQ[i + 1], a2 = lQ[i + 2];
            HQ r;
            r.x = __hadd2(__hadd2(a0.x, a1.x), a2.x);
            r.y = __hadd2(__hadd2(a0.y, a1.y), a2.y);
            r.z = __hadd2(__hadd2(a0.z, a1.z), a2.z);
            r.w = __hadd2(__hadd2(a0.w, a1.w), a2.w);
            s1Q[i] = r;
            s1E[i] = __hadd2(__hadd2(lE[i], lE[i + 1]), lE[i + 2]);
        }
        if (z < S1N - SZ) {
            const int i = SZ + z;
            HQ a0 = lQ[i], a1 = lQ[i + 1], a2 = lQ[i + 2];
            HQ r;
            r.x = __hadd2(__hadd2(a0.x, a1.x), a2.x);
            r.y = __hadd2(__hadd2(a0.y, a1.y), a2.y);
            r.z = __hadd2(__hadd2(a0.z, a1.z), a2.z);
            r.w = __hadd2(__hadd2(a0.w, a1.w), a2.w);
            s1Q[i] = r;
            s1E[i] = __hadd2(__hadd2(lE[i], lE[i + 1]), lE[i + 2]);
        }
        __syncthreads();

        // ---- phase 2: 7-tap stride-3 stage ----
        HQ s = s1Q[z];
        __half2 e = s1E[z];
#pragma unroll
        for (int j = 3; j <= 18; j += 3) {
            HQ v = s1Q[z + j];
            s.x = __hadd2(s.x, v.x);
            s.y = __hadd2(s.y, v.y);
            s.z = __hadd2(s.z, v.z);
            s.w = __hadd2(s.w, v.w);
            e = __hadd2(e, s1E[z + j]);
        }

        // ---- ring write ----
        g_rq[ro] = s;
        g_re[ro] = e;

        // ---- y running sums in native half ----
        // line0 (y): add lane0 of new pair, sub lane1 of pair it-11
        c0 = __hadd(c0, __hsub(__low2half(s.x), __high2half(hd.x)));
        c1 = __hadd(c1, __hsub(__low2half(s.y), __high2half(hd.y)));
        c2 = __hadd(c2, __hsub(__low2half(s.z), __high2half(hd.z)));
        c3 = __hadd(c3, __hsub(__low2half(s.w), __high2half(hd.w)));
        c4 = __hadd(c4, __hsub(__low2half(e),   __high2half(hed)));
        const __half a0 = c0, a1 = c1, a2 = c2, a3 = c3, a4 = c4;
        // line1 (y+1): add lane1 of new pair, sub lane0 of pair it-10
        c0 = __hadd(c0, __hsub(__high2half(s.x), __low2half(hn.x)));
        c1 = __hadd(c1, __hsub(__high2half(s.y), __low2half(hn.y)));
        c2 = __hadd(c2, __hsub(__high2half(s.z), __low2half(hn.z)));
        c3 = __hadd(c3, __hsub(__high2half(s.w), __low2half(hn.w)));
        c4 = __hadd(c4, __hsub(__high2half(e),   __low2half(hen)));

        const int yo = y - HALF;
        if (yo >= y0) {
            size_t qidx = (((size_t)(b * SX + x)) * YP + (yo >> 1)) * SZ + z;
            HQ w;
            w.x = __halves2half2(a0, c0);
            w.y = __halves2half2(a1, c1);
            w.z = __halves2half2(a2, c2);
            w.w = __halves2half2(a3, c3);
            g_q2[qidx] = w;
            g_e2[qidx] = __halves2half2(a4, c4);
        }
    }
}

// ---------------------------------------------------------------------------
// Pass C: x box filter over y-pair-packed data (two y-lines per load).
// Sliding window sums kept in NATIVE half2 (2 HADD2 per channel per step);
// converts to fp32 only at the cc evaluation. Fast division (__fdividef).
// Unroll-4 with batched loads (MLP 8). Deterministic partials; last block
// does a fixed-order final reduction.
// ---------------------------------------------------------------------------
__global__ __launch_bounds__(SZ, 6) void passC(float* __restrict__ out) {
    int bid = blockIdx.x;
    const int seg = bid % XSEG;
    int t = bid / XSEG;
    const int yp = t % YP;
    const int b = t / YP;
    const int z = threadIdx.x;

    const int x0 = seg * XLEN;
    const size_t strideX = (size_t)YP * SZ;
    const size_t base = ((size_t)b * SX) * strideX + (size_t)yp * SZ + z;

    const __half2 zero2 = __floats2half2_rn(0.f, 0.f);
    __half2 sI = zero2, sJ = zero2, sI2 = zero2, sJ2 = zero2, sIJ = zero2;

#pragma unroll
    for (int k = 0; k < WIN; k++) {
        const int xx = x0 - HALF + k;
        if (xx >= 0 && xx < SX) {
            size_t o = base + (size_t)xx * strideX;
            HQ h = g_q2[o];
            __half2 e = g_e2[o];
            sI  = __hadd2(sI,  h.x);
            sJ  = __hadd2(sJ,  h.y);
            sI2 = __hadd2(sI2, h.z);
            sJ2 = __hadd2(sJ2, h.w);
            sIJ = __hadd2(sIJ, e);
        }
    }

    const float inv_n = 1.0f / (float)(WIN * WIN * WIN);
    float acc = 0.f;

    for (int xb = 0; xb < XLEN; xb += 4) {
        HQ ha[4], hr[4];
        __half2 ea[4], er[4];
#pragma unroll
        for (int j = 0; j < 4; j++) {
            const int xa = x0 + xb + j + HALF + 1;
            ha[j].x = zero2; ha[j].y = zero2; ha[j].z = zero2; ha[j].w = zero2;
            ea[j] = zero2;
            if (xa < SX) {
                size_t o = base + (size_t)xa * strideX;
                ha[j] = g_q2[o]; ea[j] = g_e2[o];
            }
        }
#pragma unroll
        for (int j = 0; j < 4; j++) {
            const int xr = x0 + xb + j - HALF;
            hr[j].x = zero2; hr[j].y = zero2; hr[j].z = zero2; hr[j].w = zero2;
            er[j] = zero2;
            if (xr >= 0) {
                size_t o = base + (size_t)xr * strideX;
                hr[j] = g_q2[o]; er[j] = g_e2[o];
            }
        }
#pragma unroll
        for (int j = 0; j < 4; j++) {
            float2 fI  = __half22float2(sI);
            float2 fJ  = __half22float2(sJ);
            float2 fI2 = __half22float2(sI2);
            float2 fJ2 = __half22float2(sJ2);
            float2 fIJ = __half22float2(sIJ);
#pragma unroll
            for (int ln = 0; ln < 2; ln++) {
                float t0 = ln ? fI.y : fI.x;
                float t1 = ln ? fJ.y : fJ.x;
                float t2 = ln ? fI2.y : fI2.x;
                float t3 = ln ? fJ2.y : fJ2.x;
                float t4 = ln ? fIJ.y : fIJ.x;
                float cross = t4 - t0 * t1 * inv_n;
                float Ivar  = t2 - t0 * t0 * inv_n;
                float Jvar  = t3 - t1 * t1 * inv_n;
                acc += __fdividef(cross * cross, Ivar * Jvar + 1e-5f);
            }
            sI  = __hadd2(sI,  __hsub2(ha[j].x, hr[j].x));
            sJ  = __hadd2(sJ,  __hsub2(ha[j].y, hr[j].y));
            sI2 = __hadd2(sI2, __hsub2(ha[j].z, hr[j].z));
            sJ2 = __hadd2(sJ2, __hsub2(ha[j].w, hr[j].w));
            sIJ = __hadd2(sIJ, __hsub2(ea[j],   er[j]));
        }
    }

    // deterministic block reduction (160 threads = 5 warps)
    __shared__ float wsum[SZ / 32];
    __shared__ int isLast;
    float v = acc;
#pragma unroll
    for (int off = 16; off; off >>= 1)
        v += __shfl_down_sync(0xffffffffu, v, off);
    if ((threadIdx.x & 31) == 0) wsum[threadIdx.x >> 5] = v;
    __syncthreads();
    if (threadIdx.x == 0) {
        double tot = 0.0;
#pragma unroll
        for (int w = 0; w < SZ / 32; w++) tot += (double)wsum[w];
        g_part[bid] = tot;
        __threadfence();
        int n = atomicAdd(&g_count, 1);
        isLast = (n == NPART - 1);
    }
    __syncthreads();

    if (isLast) {
        __shared__ double sh[256];
        double cv = 0.0;
        const int chunk = 5;                 // 160 * 5 = 800 >= 768
        int lo = threadIdx.x * chunk;
        for (int i = lo; i < lo + chunk && i < NPART; ++i)
            cv += g_part[i];
        sh[threadIdx.x] = cv;
        if (threadIdx.x < 256 - SZ) sh[SZ + threadIdx.x] = 0.0;
        __syncthreads();
        for (int s = 128; s; s >>= 1) {
            if (threadIdx.x < s) sh[threadIdx.x] += sh[threadIdx.x + s];
            __syncthreads();
        }
        if (threadIdx.x == 0) {
            out[0] = (float)(1.0 - sh[0] / (double)NF);
            g_count = 0;                      // reset for next graph replay
        }
    }
}

extern "C" void kernel_launch(void* const* d_in, const int* in_sizes, int n_in,
                              void* d_out, int out_size) {
    const float* I = (const float*)d_in[0];
    const float* J = (const float*)d_in[1];
    float* out = (float*)d_out;

    passAB<<<NBLK_AB, SZ>>>(I, J);
    passC<<<NPART, SZ>>>(out);
}